// round 2
// baseline (speedup 1.0000x reference)
#include <cuda_runtime.h>

#define DIM        128
#define NUM_RELS   8
#define CHUNK      2048
#define TILE       32
#define NTHREADS   256

// Dynamic smem layout:
//   W   : DIM*DIM floats          (65536 B)
//   X   : TILE*DIM floats         (16384 B)
//   list: CHUNK ints              ( 8192 B)
#define SMEM_BYTES (DIM*DIM*4 + TILE*DIM*4 + CHUNK*4)

extern __shared__ float g_smem[];

__global__ void __launch_bounds__(NTHREADS, 2)
rgcn_edge_kernel(const float* __restrict__ feat,
                 const float* __restrict__ rel_emb,
                 const float* __restrict__ ew,
                 const int*   __restrict__ src,
                 const int*   __restrict__ dst,
                 const int*   __restrict__ rel,
                 float*       __restrict__ out,
                 int n_edges)
{
    float* Wsh  = g_smem;                       // [DIM][DIM]
    float* Xsh  = g_smem + DIM * DIM;           // [TILE][DIM]
    int*   list = (int*)(Xsh + TILE * DIM);     // [CHUNK]
    __shared__ int cnt;

    const int r    = blockIdx.y;
    const int tid  = threadIdx.x;
    const int warp = tid >> 5;
    const int lane = tid & 31;

    // Stage W_r (row-major [k][col]) into smem as float4s.
    {
        const float4* Wg = (const float4*)(rel_emb + (size_t)r * DIM * DIM);
        float4* W4 = (float4*)Wsh;
        #pragma unroll
        for (int i = tid; i < DIM * DIM / 4; i += NTHREADS) W4[i] = Wg[i];
    }
    if (tid == 0) cnt = 0;
    __syncthreads();

    // Compact this chunk's edges that belong to relation r.
    const int base = blockIdx.x * CHUNK;
    const int end  = min(base + CHUNK, n_edges);
    for (int e = base + tid; e < end; e += NTHREADS) {
        if (rel[e] == r) {
            int p = atomicAdd(&cnt, 1);
            list[p] = e;
        }
    }
    __syncthreads();
    const int total = cnt;

    const float4* Wv = (const float4*)Wsh;   // [k][32 float4 cols]

    for (int t0 = 0; t0 < total; t0 += TILE) {
        const int nvalid = min(TILE, total - t0);

        // Gather: 8 threads per row, each loads 16 floats (4x float4), scaled by edge weight.
        {
            const int row  = tid >> 3;          // 0..31
            const int cseg = (tid & 7) * 16;    // 16-float segment
            float4* xr = (float4*)(Xsh + row * DIM + cseg);
            if (row < nvalid) {
                const int   e = list[t0 + row];
                const int   s = src[e];
                const float w = ew[e];
                const float4* fr = (const float4*)(feat + (size_t)s * DIM + cseg);
                #pragma unroll
                for (int q = 0; q < 4; q++) {
                    float4 v = fr[q];
                    v.x *= w; v.y *= w; v.z *= w; v.w *= w;
                    xr[q] = v;
                }
            } else {
                const float4 z = make_float4(0.f, 0.f, 0.f, 0.f);
                #pragma unroll
                for (int q = 0; q < 4; q++) xr[q] = z;
            }
        }
        __syncthreads();

        // Compute: warp -> rows [4*warp, 4*warp+3]; lane -> cols [4*lane, 4*lane+3].
        float4 acc0 = make_float4(0.f,0.f,0.f,0.f);
        float4 acc1 = acc0, acc2 = acc0, acc3 = acc0;

        const float4* X0 = (const float4*)(Xsh + (warp * 4 + 0) * DIM);
        const float4* X1 = (const float4*)(Xsh + (warp * 4 + 1) * DIM);
        const float4* X2 = (const float4*)(Xsh + (warp * 4 + 2) * DIM);
        const float4* X3 = (const float4*)(Xsh + (warp * 4 + 3) * DIM);

        #pragma unroll 8
        for (int k4 = 0; k4 < DIM / 4; k4++) {
            const float4 a4 = X0[k4];
            const float4 b4 = X1[k4];
            const float4 c4 = X2[k4];
            const float4 d4 = X3[k4];
            const float xa[4] = {a4.x, a4.y, a4.z, a4.w};
            const float xb[4] = {b4.x, b4.y, b4.z, b4.w};
            const float xc[4] = {c4.x, c4.y, c4.z, c4.w};
            const float xd[4] = {d4.x, d4.y, d4.z, d4.w};
            #pragma unroll
            for (int q = 0; q < 4; q++) {
                const float4 wv = Wv[(k4 * 4 + q) * 32 + lane];
                acc0.x += xa[q] * wv.x; acc0.y += xa[q] * wv.y;
                acc0.z += xa[q] * wv.z; acc0.w += xa[q] * wv.w;
                acc1.x += xb[q] * wv.x; acc1.y += xb[q] * wv.y;
                acc1.z += xb[q] * wv.z; acc1.w += xb[q] * wv.w;
                acc2.x += xc[q] * wv.x; acc2.y += xc[q] * wv.y;
                acc2.z += xc[q] * wv.z; acc2.w += xc[q] * wv.w;
                acc3.x += xd[q] * wv.x; acc3.y += xd[q] * wv.y;
                acc3.z += xd[q] * wv.z; acc3.w += xd[q] * wv.w;
            }
        }

        // Scatter: vector atomics (16B-aligned: lane*4 floats).
        {
            float4 accs[4] = {acc0, acc1, acc2, acc3};
            #pragma unroll
            for (int i = 0; i < 4; i++) {
                const int rowt = warp * 4 + i;
                if (rowt < nvalid) {
                    const int e = list[t0 + rowt];
                    const int d = dst[e];
                    float* p = out + (size_t)d * DIM + lane * 4;
                    asm volatile("red.global.add.v4.f32 [%0], {%1, %2, %3, %4};"
                                 :: "l"(p), "f"(accs[i].x), "f"(accs[i].y),
                                    "f"(accs[i].z), "f"(accs[i].w)
                                 : "memory");
                }
            }
        }
        __syncthreads();   // protect Xsh before next tile's gather
    }
}

extern "C" void kernel_launch(void* const* d_in, const int* in_sizes, int n_in,
                              void* d_out, int out_size)
{
    const float* feat    = (const float*)d_in[0];
    const float* rel_emb = (const float*)d_in[1];
    const float* ew      = (const float*)d_in[2];
    const int*   src     = (const int*)d_in[3];
    const int*   dst     = (const int*)d_in[4];
    const int*   rel     = (const int*)d_in[5];
    float*       out     = (float*)d_out;

    const int n_edges = in_sizes[2];

    // Output is poisoned; we accumulate with atomics, so zero it first.
    cudaMemsetAsync(d_out, 0, (size_t)out_size * sizeof(float), 0);

    static int smem_set = 0; // idempotent attribute set (host-side, not a graph node)
    if (!smem_set) {
        cudaFuncSetAttribute(rgcn_edge_kernel,
                             cudaFuncAttributeMaxDynamicSharedMemorySize, SMEM_BYTES);
        smem_set = 1;
    }

    dim3 grid((n_edges + CHUNK - 1) / CHUNK, NUM_RELS);
    rgcn_edge_kernel<<<grid, NTHREADS, SMEM_BYTES>>>(
        feat, rel_emb, ew, src, dst, rel, out, n_edges);
}

// round 4
// speedup vs baseline: 1.4076x; 1.4076x over previous
#include <cuda_runtime.h>
#include <cuda_bf16.h>
#include <cstdint>

// ════════════════════════════════════════════════════════════════════════
// out[dst] += (feat[src] @ W[rel]) * ew   — 800k edges, 8 rels, 128x128
// Counting-sort edges by relation, then bf16-split HMMA (mma.sync) GEMM:
// acc = Ahi*Whi + Ahi*Wlo + Alo*Whi  (fp32 accum), scatter via red.v4.f32.
// (tcgen05 unavailable: harness lowers through compute_103, no 'a' target.)
// ════════════════════════════════════════════════════════════════════════

#define DIM       128
#define NUM_RELS  8
#define MAX_E     1048576
#define P1_CHUNK  4096
#define MAX_B     ((MAX_E + P1_CHUNK - 1) / P1_CHUNK)   // 256
#define MAX_TILES (MAX_E / 128 + NUM_RELS)

#define ASTRIDE   136            // bf16 elems per row (128 + 8 pad) -> 272 B
#define ROWB      272            // bytes per padded bf16 row
#define CSTRIDE   132            // f32 elems per staged-C row -> 528 B

// SMEM layout (bytes):
//   As_hi [128][136] bf16 : off 0      size 34816
//   As_lo                  : off 34816
//   Ws_hi [128][136] bf16 : off 69632
//   Ws_lo                  : off 104448
//   total 139264.  C staging [128][132] f32 (67584 B) aliases As region.
#define OFF_AHI   0
#define OFF_ALO   34816
#define OFF_WHI   69632
#define OFF_WLO   104448
#define SMEM_MAIN 139264

// ---- device scratch ----
__device__ int            g_bh[MAX_B * 8];
__device__ int            g_relStart[9];
__device__ int            g_perm[MAX_E];
__device__ int            g_tileRel[MAX_TILES];
__device__ int            g_tileStart[MAX_TILES];
__device__ int            g_nTiles;
__device__ __nv_bfloat16  g_Wpk[NUM_RELS][2][DIM * DIM];  // [rel][hi/lo][k*128+n]

// ════════════════ PTX helpers ═══════════════════════════════════════════
__device__ __forceinline__ uint32_t smem_u32(const void* p) {
    uint32_t a;
    asm("{ .reg .u64 t; cvta.to.shared.u64 t, %1; cvt.u32.u64 %0, t; }" : "=r"(a) : "l"(p));
    return a;
}
__device__ __forceinline__ void ldsm_x4(uint32_t* r, uint32_t addr) {
    asm volatile("ldmatrix.sync.aligned.m8n8.x4.shared.b16 {%0,%1,%2,%3}, [%4];"
                 : "=r"(r[0]), "=r"(r[1]), "=r"(r[2]), "=r"(r[3]) : "r"(addr));
}
__device__ __forceinline__ void ldsm_x4_t(uint32_t* r, uint32_t addr) {
    asm volatile("ldmatrix.sync.aligned.m8n8.x4.trans.shared.b16 {%0,%1,%2,%3}, [%4];"
                 : "=r"(r[0]), "=r"(r[1]), "=r"(r[2]), "=r"(r[3]) : "r"(addr));
}
__device__ __forceinline__ void mma16816(float* d, const uint32_t* a, const uint32_t* b) {
    asm volatile("mma.sync.aligned.m16n8k16.row.col.f32.bf16.bf16.f32 "
                 "{%0,%1,%2,%3}, {%4,%5,%6,%7}, {%8,%9}, {%0,%1,%2,%3};"
                 : "+f"(d[0]), "+f"(d[1]), "+f"(d[2]), "+f"(d[3])
                 : "r"(a[0]), "r"(a[1]), "r"(a[2]), "r"(a[3]), "r"(b[0]), "r"(b[1]));
}

// ════════════════ prep kernels ══════════════════════════════════════════
__global__ void repack_w_kernel(const float* __restrict__ rel_emb) {
    const int r = blockIdx.x;
    __nv_bfloat16* hi = &g_Wpk[r][0][0];
    __nv_bfloat16* lo = &g_Wpk[r][1][0];
    for (int idx = threadIdx.x; idx < DIM * DIM; idx += blockDim.x) {
        const float w = rel_emb[r * DIM * DIM + idx];   // [k][n] row-major, kept as-is
        const __nv_bfloat16 h = __float2bfloat16(w);
        hi[idx] = h;
        lo[idx] = __float2bfloat16(w - __bfloat162float(h));
    }
}

__global__ void count_kernel(const int* __restrict__ rel, int n) {
    __shared__ int h[8];
    if (threadIdx.x < 8) h[threadIdx.x] = 0;
    __syncthreads();
    const int base = blockIdx.x * P1_CHUNK;
    const int end  = min(base + P1_CHUNK, n);
    for (int e = base + threadIdx.x; e < end; e += blockDim.x)
        atomicAdd(&h[rel[e]], 1);
    __syncthreads();
    if (threadIdx.x < 8) g_bh[blockIdx.x * 8 + threadIdx.x] = h[threadIdx.x];
}

__global__ void scan_kernel(int nB) {
    __shared__ int s_bh[MAX_B * 8];
    __shared__ int s_rs[9];
    __shared__ int s_to[9];
    const int tid = threadIdx.x;
    for (int i = tid; i < nB * 8; i += blockDim.x) s_bh[i] = g_bh[i];
    __syncthreads();
    if (tid < 8) {
        int tot = 0;
        for (int b = 0; b < nB; b++) tot += s_bh[b * 8 + tid];
        s_rs[tid + 1] = tot;
    }
    if (tid == 0) s_rs[0] = 0;
    __syncthreads();
    if (tid == 0) {
        for (int r = 0; r < 8; r++) s_rs[r + 1] += s_rs[r];
        int to = 0;
        for (int r = 0; r < 8; r++) {
            s_to[r] = to;
            to += (s_rs[r + 1] - s_rs[r] + 127) >> 7;
        }
        s_to[8] = to;
        g_nTiles = to;
    }
    __syncthreads();
    if (tid < 8) {
        int off = s_rs[tid];
        for (int b = 0; b < nB; b++) {
            int v = s_bh[b * 8 + tid];
            s_bh[b * 8 + tid] = off;
            off += v;
        }
    }
    __syncthreads();
    for (int i = tid; i < nB * 8; i += blockDim.x) g_bh[i] = s_bh[i];
    if (tid < 9) g_relStart[tid] = s_rs[tid];
    __syncthreads();
    for (int r = 0; r < 8; r++) {
        const int st = s_rs[r];
        const int nt = (s_rs[r + 1] - st + 127) >> 7;
        for (int i = tid; i < nt; i += blockDim.x) {
            g_tileRel[s_to[r] + i]   = r;
            g_tileStart[s_to[r] + i] = st + i * 128;
        }
    }
}

__global__ void scatter_perm_kernel(const int* __restrict__ rel, int n) {
    __shared__ int off[8];
    if (threadIdx.x < 8) off[threadIdx.x] = g_bh[blockIdx.x * 8 + threadIdx.x];
    __syncthreads();
    const int base = blockIdx.x * P1_CHUNK;
    const int end  = min(base + P1_CHUNK, n);
    for (int e = base + threadIdx.x; e < end; e += blockDim.x) {
        const int p = atomicAdd(&off[rel[e]], 1);
        g_perm[p] = e;
    }
}

// ════════════════ main GEMM kernel ══════════════════════════════════════
__global__ void __launch_bounds__(256, 1)
rgcn_mma_kernel(const float* __restrict__ feat,
                const float* __restrict__ ew,
                const int*   __restrict__ src,
                const int*   __restrict__ dst,
                float*       __restrict__ out)
{
    const int t = blockIdx.x;
    if (t >= g_nTiles) return;

    extern __shared__ char smem[];
    const uint32_t sbase = smem_u32(smem);
    const int tid  = threadIdx.x;
    const int wid  = tid >> 5;
    const int lane = tid & 31;

    const int r     = g_tileRel[t];
    const int start = g_tileStart[t];
    const int cnt   = min(128, g_relStart[r + 1] - start);

    // ── W (hi|lo) -> SMEM, padded rows ──
    {
        const uint4* whg = (const uint4*)&g_Wpk[r][0][0];
        const uint4* wlg = (const uint4*)&g_Wpk[r][1][0];
        #pragma unroll
        for (int i = tid; i < 2048; i += 256) {            // 2048 uint4 per image
            const int row = i >> 4, c16 = i & 15;
            const int doff = row * ROWB + c16 * 16;
            *(uint4*)(smem + OFF_WHI + doff) = whg[i];
            *(uint4*)(smem + OFF_WLO + doff) = wlg[i];
        }
    }

    // ── Gather + weight + bf16 split -> SMEM A (hi|lo) ──
    {
        const int row = tid >> 1;               // 0..127
        const int seg = tid & 1;                // 64-col half
        const bool valid = row < cnt;
        const float4* fr = nullptr;
        float w = 0.f;
        if (valid) {
            const int e = g_perm[start + row];
            w  = ew[e];
            fr = (const float4*)(feat + (size_t)src[e] * DIM);
        }
        const int kbase = seg * 64;
        char* ah = smem + OFF_AHI + row * ROWB + kbase * 2;
        char* al = smem + OFF_ALO + row * ROWB + kbase * 2;
        #pragma unroll
        for (int j = 0; j < 16; j++) {
            uint2 hp, lp;
            if (valid) {
                float4 v = fr[seg * 16 + j];
                v.x *= w; v.y *= w; v.z *= w; v.w *= w;
                __nv_bfloat162 h0, h1, l0, l1;
                h0.x = __float2bfloat16(v.x); l0.x = __float2bfloat16(v.x - __bfloat162float(h0.x));
                h0.y = __float2bfloat16(v.y); l0.y = __float2bfloat16(v.y - __bfloat162float(h0.y));
                h1.x = __float2bfloat16(v.z); l1.x = __float2bfloat16(v.z - __bfloat162float(h1.x));
                h1.y = __float2bfloat16(v.w); l1.y = __float2bfloat16(v.w - __bfloat162float(h1.y));
                hp.x = *(uint32_t*)&h0; hp.y = *(uint32_t*)&h1;
                lp.x = *(uint32_t*)&l0; lp.y = *(uint32_t*)&l1;
            } else {
                hp = make_uint2(0u, 0u); lp = make_uint2(0u, 0u);
            }
            *(uint2*)(ah + j * 8) = hp;
            *(uint2*)(al + j * 8) = lp;
        }
    }
    __syncthreads();

    // ── Mainloop: warp -> M=32 x N=64; 3 chains x 8 k16-steps ──
    const int m_base = (wid >> 1) * 32;
    const int n_base = (wid & 1) * 64;

    float acc[2][8][4];
    #pragma unroll
    for (int mt = 0; mt < 2; mt++)
        #pragma unroll
        for (int nt = 0; nt < 8; nt++)
            #pragma unroll
            for (int q = 0; q < 4; q++) acc[mt][nt][q] = 0.f;

    // per-lane ldmatrix address components
    const uint32_t a_lane = (uint32_t)((lane & 15) * ROWB + (lane >> 4) * 16);
    const uint32_t b_lane = (uint32_t)((lane & 15) * ROWB + ((lane >> 4) & 1) * 16);

    #pragma unroll
    for (int c = 0; c < 3; c++) {
        const uint32_t Ab = sbase + (c == 2 ? OFF_ALO : OFF_AHI);
        const uint32_t Wb = sbase + (c == 1 ? OFF_WLO : OFF_WHI);
        #pragma unroll
        for (int ks = 0; ks < 8; ks++) {
            uint32_t afr[2][4];
            #pragma unroll
            for (int mt = 0; mt < 2; mt++)
                ldsm_x4(afr[mt], Ab + (uint32_t)((m_base + mt * 16) * ROWB) + a_lane
                                    + (uint32_t)(ks * 32));
            uint32_t bfr[4][4];      // pair p -> ntiles 2p, 2p+1
            #pragma unroll
            for (int p = 0; p < 4; p++)
                ldsm_x4_t(bfr[p], Wb + (uint32_t)(ks * 16 * ROWB) + b_lane
                                     + (uint32_t)((n_base + p * 16) * 2));
            #pragma unroll
            for (int mt = 0; mt < 2; mt++)
                #pragma unroll
                for (int p = 0; p < 4; p++) {
                    mma16816(acc[mt][2 * p + 0], afr[mt], &bfr[p][0]);
                    mma16816(acc[mt][2 * p + 1], afr[mt], &bfr[p][2]);
                }
        }
    }
    __syncthreads();     // mainloop done; A region now reusable as C staging

    // ── Stage C into SMEM (f32, stride 132) ──
    {
        float* Cst = (float*)smem;           // aliases As region
        const int grp = lane >> 2;           // 0..7
        const int tig = lane & 3;            // 0..3
        #pragma unroll
        for (int mt = 0; mt < 2; mt++) {
            const int r0 = m_base + mt * 16 + grp;
            #pragma unroll
            for (int nt = 0; nt < 8; nt++) {
                const int col = n_base + nt * 8 + tig * 2;
                *(float2*)&Cst[r0 * CSTRIDE + col]       = make_float2(acc[mt][nt][0], acc[mt][nt][1]);
                *(float2*)&Cst[(r0 + 8) * CSTRIDE + col] = make_float2(acc[mt][nt][2], acc[mt][nt][3]);
            }
        }
    }
    __syncthreads();

    // ── Scatter: warp w -> rows [16w, 16w+16), one red.v4 per lane per row ──
    {
        const float* Cst = (const float*)smem;
        #pragma unroll
        for (int i = 0; i < 16; i++) {
            const int row = wid * 16 + i;
            if (row < cnt) {
                const int e = g_perm[start + row];
                const int d = dst[e];
                const float4 v = *(const float4*)&Cst[row * CSTRIDE + lane * 4];
                float* p = out + (size_t)d * DIM + lane * 4;
                asm volatile("red.global.add.v4.f32 [%0], {%1, %2, %3, %4};"
                             :: "l"(p), "f"(v.x), "f"(v.y), "f"(v.z), "f"(v.w)
                             : "memory");
            }
        }
    }
}

// ════════════════ launch ════════════════════════════════════════════════
extern "C" void kernel_launch(void* const* d_in, const int* in_sizes, int n_in,
                              void* d_out, int out_size)
{
    const float* feat    = (const float*)d_in[0];
    const float* rel_emb = (const float*)d_in[1];
    const float* ew      = (const float*)d_in[2];
    const int*   src     = (const int*)d_in[3];
    const int*   dst     = (const int*)d_in[4];
    const int*   rel     = (const int*)d_in[5];
    float*       out     = (float*)d_out;

    const int n_edges  = in_sizes[2];
    const int nB       = (n_edges + P1_CHUNK - 1) / P1_CHUNK;
    const int maxTiles = n_edges / 128 + NUM_RELS + 1;

    static int attr_set = 0;
    if (!attr_set) {
        cudaFuncSetAttribute(rgcn_mma_kernel,
                             cudaFuncAttributeMaxDynamicSharedMemorySize, SMEM_MAIN);
        attr_set = 1;
    }

    cudaMemsetAsync(d_out, 0, (size_t)out_size * sizeof(float), 0);
    repack_w_kernel<<<NUM_RELS, 256>>>(rel_emb);
    count_kernel<<<nB, 256>>>(rel, n_edges);
    scan_kernel<<<1, 256>>>(nB);
    scatter_perm_kernel<<<nB, 256>>>(rel, n_edges);
    rgcn_mma_kernel<<<maxTiles, 256, SMEM_MAIN>>>(feat, ew, src, dst, out);
}

// round 6
// speedup vs baseline: 2.3642x; 1.6796x over previous
#include <cuda_runtime.h>
#include <cuda_fp16.h>
#include <cstdint>

// ════════════════════════════════════════════════════════════════════════
// out[dst] += (feat[src] @ W[rel]) * ew  — aggregate-first formulation:
//   Phase 1 (edge):  H[r][dst] += w * feat[src]        (fp32 red.v4 atomics)
//   Phase 2 (GEMM):  out[n]     = Σ_r H[r][n] @ W_r    (dense fp16 HMMA,
//                                  W split hi/lo 2-chain, fp32 accum, no atomics)
// Halves MMA FLOPs vs edge-wise, removes sorting and output atomics entirely.
// ════════════════════════════════════════════════════════════════════════

#define DIM       128
#define NUM_RELS  8
#define MAXN_PAD  65536
#define ROWB      272            // padded fp16 row: 136 halves = 272 B
#define CSTRIDE   132            // staged-C f32 row stride

// SMEM (GEMM kernel): A fp16 [128][136] @0 (34816 B), Whi @34816, Wlo @69632.
// C staging [128][132] f32 (67584 B) aliases A+Whi after the mainloop.
#define OFF_A     0
#define OFF_WHI   34816
#define OFF_WLO   69632
#define SMEM_MAIN 104448

// ---- device scratch ----
__device__ float  g_H[(size_t)NUM_RELS * MAXN_PAD * DIM];   // 268 MB
__device__ __half g_Wh[NUM_RELS][DIM * DIM];
__device__ __half g_Wl[NUM_RELS][DIM * DIM];

// ════════════════ PTX helpers ═══════════════════════════════════════════
__device__ __forceinline__ uint32_t smem_u32(const void* p) {
    uint32_t a;
    asm("{ .reg .u64 t; cvta.to.shared.u64 t, %1; cvt.u32.u64 %0, t; }" : "=r"(a) : "l"(p));
    return a;
}
__device__ __forceinline__ void ldsm_x4(uint32_t* r, uint32_t addr) {
    asm volatile("ldmatrix.sync.aligned.m8n8.x4.shared.b16 {%0,%1,%2,%3}, [%4];"
                 : "=r"(r[0]), "=r"(r[1]), "=r"(r[2]), "=r"(r[3]) : "r"(addr));
}
__device__ __forceinline__ void ldsm_x4_t(uint32_t* r, uint32_t addr) {
    asm volatile("ldmatrix.sync.aligned.m8n8.x4.trans.shared.b16 {%0,%1,%2,%3}, [%4];"
                 : "=r"(r[0]), "=r"(r[1]), "=r"(r[2]), "=r"(r[3]) : "r"(addr));
}
__device__ __forceinline__ void mma16816(float* d, const uint32_t* a, const uint32_t* b) {
    asm volatile("mma.sync.aligned.m16n8k16.row.col.f32.f16.f16.f32 "
                 "{%0,%1,%2,%3}, {%4,%5,%6,%7}, {%8,%9}, {%0,%1,%2,%3};"
                 : "+f"(d[0]), "+f"(d[1]), "+f"(d[2]), "+f"(d[3])
                 : "r"(a[0]), "r"(a[1]), "r"(a[2]), "r"(a[3]), "r"(b[0]), "r"(b[1]));
}

// ════════════════ prep: W -> fp16 hi/lo split ═══════════════════════════
__global__ void repack_w_kernel(const float* __restrict__ rel_emb) {
    const int r = blockIdx.x;
    for (int idx = threadIdx.x; idx < DIM * DIM; idx += blockDim.x) {
        const float w = rel_emb[r * DIM * DIM + idx];       // [k][n] row-major
        const __half h = __float2half(w);
        g_Wh[r][idx] = h;
        g_Wl[r][idx] = __float2half(w - __half2float(h));
    }
}

// ════════════════ Phase 1: edge aggregation ═════════════════════════════
// warp handles 32 consecutive edges; per edge: 1 LDG.128 gather + 1 red.v4.
__global__ void __launch_bounds__(256)
edge_agg_kernel(const float* __restrict__ feat,
                const float* __restrict__ ew,
                const int*   __restrict__ src,
                const int*   __restrict__ dst,
                const int*   __restrict__ rel,
                int n_edges, int npad)
{
    const int lane = threadIdx.x & 31;
    const int gw   = (blockIdx.x * blockDim.x + threadIdx.x) >> 5;
    const int base = gw * 32;
    if (base >= n_edges) return;
    const int cnt = min(32, n_edges - base);

    int s = 0, d = 0, r = 0; float w = 0.f;
    if (lane < cnt) {
        const int e = base + lane;
        s = src[e]; d = dst[e]; r = rel[e]; w = ew[e];
    }

    for (int i = 0; i < cnt; i++) {
        const int   si = __shfl_sync(0xFFFFFFFFu, s, i);
        const int   di = __shfl_sync(0xFFFFFFFFu, d, i);
        const int   ri = __shfl_sync(0xFFFFFFFFu, r, i);
        const float wi = __shfl_sync(0xFFFFFFFFu, w, i);

        float4 v = *(const float4*)(feat + (size_t)si * DIM + lane * 4);
        v.x *= wi; v.y *= wi; v.z *= wi; v.w *= wi;

        float* p = g_H + ((size_t)ri * npad + di) * DIM + lane * 4;
        asm volatile("red.global.add.v4.f32 [%0], {%1, %2, %3, %4};"
                     :: "l"(p), "f"(v.x), "f"(v.y), "f"(v.z), "f"(v.w)
                     : "memory");
    }
}

// ════════════════ Phase 2: dense GEMM, accumulate over 8 rels ═══════════
__global__ void __launch_bounds__(256, 2)
gemm_kernel(float* __restrict__ out, int n_nodes, int npad)
{
    extern __shared__ char smem[];
    const uint32_t sbase = smem_u32(smem);
    const int tid  = threadIdx.x;
    const int wid  = tid >> 5;
    const int lane = tid & 31;

    const int tile0 = blockIdx.x * 128;
    const int n_rem = min(128, n_nodes - tile0);

    const int m_base = (wid >> 1) * 32;
    const int n_base = (wid & 1) * 64;

    float acc[2][8][4];
    #pragma unroll
    for (int mt = 0; mt < 2; mt++)
        #pragma unroll
        for (int nt = 0; nt < 8; nt++)
            #pragma unroll
            for (int q = 0; q < 4; q++) acc[mt][nt][q] = 0.f;

    const uint32_t a_lane = (uint32_t)((lane & 15) * ROWB + (lane >> 4) * 16);
    const uint32_t b_lane = (uint32_t)((lane & 15) * ROWB + ((lane >> 4) & 1) * 16);

    for (int r = 0; r < NUM_RELS; r++) {
        __syncthreads();   // smem reuse safety vs previous rel's MMA

        // W_r hi/lo -> smem (padded rows)
        {
            const uint4* whg = (const uint4*)&g_Wh[r][0];
            const uint4* wlg = (const uint4*)&g_Wl[r][0];
            #pragma unroll
            for (int i = tid; i < 2048; i += 256) {
                const int row = i >> 4, c16 = i & 15;
                const int doff = row * ROWB + c16 * 16;
                *(uint4*)(smem + OFF_WHI + doff) = whg[i];
                *(uint4*)(smem + OFF_WLO + doff) = wlg[i];
            }
        }
        // A = H_r tile -> fp16 smem (sequential loads, pad rows are zero)
        {
            const int row = tid >> 1;
            const int seg = tid & 1;
            const float4* hr = (const float4*)
                (g_H + ((size_t)r * npad + tile0 + row) * DIM + seg * 64);
            char* ap = smem + OFF_A + row * ROWB + seg * 128;
            #pragma unroll
            for (int j = 0; j < 16; j++) {
                const float4 v = hr[j];
                __half2 h0, h1;
                h0.x = __float2half(v.x); h0.y = __float2half(v.y);
                h1.x = __float2half(v.z); h1.y = __float2half(v.w);
                uint2 pk;
                pk.x = *(uint32_t*)&h0; pk.y = *(uint32_t*)&h1;
                *(uint2*)(ap + j * 8) = pk;
            }
        }
        __syncthreads();

        // Mainloop: per k16-step load A frags once, run Whi + Wlo chains.
        #pragma unroll
        for (int ks = 0; ks < 8; ks++) {
            uint32_t afr[2][4];
            #pragma unroll
            for (int mt = 0; mt < 2; mt++)
                ldsm_x4(afr[mt], sbase + OFF_A + (uint32_t)((m_base + mt * 16) * ROWB)
                                 + a_lane + (uint32_t)(ks * 32));
            #pragma unroll
            for (int c = 0; c < 2; c++) {
                const uint32_t Wb = sbase + (c ? OFF_WLO : OFF_WHI);
                uint32_t bfr[4][4];
                #pragma unroll
                for (int p = 0; p < 4; p++)
                    ldsm_x4_t(bfr[p], Wb + (uint32_t)(ks * 16 * ROWB) + b_lane
                                         + (uint32_t)((n_base + p * 16) * 2));
                #pragma unroll
                for (int mt = 0; mt < 2; mt++)
                    #pragma unroll
                    for (int p = 0; p < 4; p++) {
                        mma16816(acc[mt][2 * p + 0], afr[mt], &bfr[p][0]);
                        mma16816(acc[mt][2 * p + 1], afr[mt], &bfr[p][2]);
                    }
            }
        }
    }
    __syncthreads();   // mainloop done; A/W smem reusable as C staging

    // Stage C (f32) into smem, then coalesced guarded stores — NO atomics.
    {
        float* Cst = (float*)smem;
        const int grp = lane >> 2;
        const int tig = lane & 3;
        #pragma unroll
        for (int mt = 0; mt < 2; mt++) {
            const int r0 = m_base + mt * 16 + grp;
            #pragma unroll
            for (int nt = 0; nt < 8; nt++) {
                const int col = n_base + nt * 8 + tig * 2;
                *(float2*)&Cst[r0 * CSTRIDE + col]       = make_float2(acc[mt][nt][0], acc[mt][nt][1]);
                *(float2*)&Cst[(r0 + 8) * CSTRIDE + col] = make_float2(acc[mt][nt][2], acc[mt][nt][3]);
            }
        }
    }
    __syncthreads();
    {
        const float* Cst = (const float*)smem;
        const int row = tid >> 1;
        const int seg = tid & 1;
        if (row < n_rem) {
            float4* op = (float4*)(out + (size_t)(tile0 + row) * DIM + seg * 64);
            const float* cp = &Cst[row * CSTRIDE + seg * 64];
            #pragma unroll
            for (int j = 0; j < 16; j++)
                op[j] = *(const float4*)(cp + j * 4);
        }
    }
}

// ════════════════ launch ════════════════════════════════════════════════
extern "C" void kernel_launch(void* const* d_in, const int* in_sizes, int n_in,
                              void* d_out, int out_size)
{
    const float* feat    = (const float*)d_in[0];
    const float* rel_emb = (const float*)d_in[1];
    const float* ew      = (const float*)d_in[2];
    const int*   src     = (const int*)d_in[3];
    const int*   dst     = (const int*)d_in[4];
    const int*   rel     = (const int*)d_in[5];
    float*       out     = (float*)d_out;

    const int n_edges = in_sizes[2];
    const int n_nodes = in_sizes[0] / DIM;
    int npad = ((n_nodes + 127) / 128) * 128;
    if (npad > MAXN_PAD) npad = MAXN_PAD;

    static void* h_ptr = nullptr;
    static int attr_set = 0;
    if (!attr_set) {
        cudaGetSymbolAddress(&h_ptr, g_H);
        cudaFuncSetAttribute(gemm_kernel,
                             cudaFuncAttributeMaxDynamicSharedMemorySize, SMEM_MAIN);
        attr_set = 1;
    }

    // zero H (covers all 8 rel planes incl. pad rows)
    cudaMemsetAsync(h_ptr, 0, (size_t)NUM_RELS * npad * DIM * sizeof(float), 0);

    repack_w_kernel<<<NUM_RELS, 256>>>(rel_emb);

    const int edge_ctas = (n_edges + 255) / 256;     // 8 warps x 32 edges each
    edge_agg_kernel<<<edge_ctas, 256>>>(feat, ew, src, dst, rel, n_edges, npad);

    const int tiles = (n_nodes + 127) / 128;
    gemm_kernel<<<tiles, 256, SMEM_MAIN>>>(out, n_nodes, npad);
}

// round 7
// speedup vs baseline: 2.7745x; 1.1735x over previous
#include <cuda_runtime.h>
#include <cuda_fp16.h>
#include <cstdint>

// ════════════════════════════════════════════════════════════════════════
// out[dst] = Σ_r (Σ_{e: rel=r} w_e · feat[src_e]) @ W_r  — fused design:
//   sort edges by (dst_tile, rel)  →  one CTA per dst tile:
//     per rel: smem-local sort by dst&127, register aggregation (no atomics),
//              A tile fp16, 2-chain W-split HMMA accumulated over rels,
//              plain coalesced stores.  No H buffer, no global atomics.
// ════════════════════════════════════════════════════════════════════════

#define DIM       128
#define NUM_RELS  8
#define MAX_E     1048576
#define MAX_TILES 512
#define MAX_BINS  (MAX_TILES * NUM_RELS)
#define CAP       512              // staged edges per chunk
#define ROWB      272              // padded fp16 row: 136 halves
#define CSTRIDE   132              // staged-C f32 row stride

// SMEM layout (bytes) for the fused kernel:
#define OFF_A     0                // fp16 A [128][136]     34816
#define OFF_WHI   34816            // fp16 Whi [128][136]   34816
#define OFF_WLO   69632            // fp16 Wlo [128][136]   34816
#define OFF_SSRC  104448           // int  [CAP]             2048
#define OFF_SW    106496           // f32  [CAP]             2048
#define OFF_SDL   108544           // int  [CAP]             2048
#define OFF_OSRC  110592           // int  [CAP]             2048
#define OFF_OW    112640           // f32  [CAP]             2048
#define OFF_HIST  114688           // int  [128]              512
#define OFF_RS    115200           // int  [129]              528 (padded)
#define OFF_CUR   115728           // int  [128]              512
#define SMEM_F    116352
// C staging [128][132] f32 (67584 B) aliases OFF_A.. after the mainloop.

// ---- device scratch ----
__device__ int    g_binCnt[MAX_BINS];
__device__ int    g_binOff[MAX_BINS + 1];
__device__ int    g_binCur[MAX_BINS];
__device__ int    g_eidx[MAX_E];
__device__ __half g_Wh[NUM_RELS][DIM * DIM];
__device__ __half g_Wl[NUM_RELS][DIM * DIM];

// ════════════════ PTX helpers ═══════════════════════════════════════════
__device__ __forceinline__ uint32_t smem_u32(const void* p) {
    uint32_t a;
    asm("{ .reg .u64 t; cvta.to.shared.u64 t, %1; cvt.u32.u64 %0, t; }" : "=r"(a) : "l"(p));
    return a;
}
__device__ __forceinline__ void ldsm_x4(uint32_t* r, uint32_t addr) {
    asm volatile("ldmatrix.sync.aligned.m8n8.x4.shared.b16 {%0,%1,%2,%3}, [%4];"
                 : "=r"(r[0]), "=r"(r[1]), "=r"(r[2]), "=r"(r[3]) : "r"(addr));
}
__device__ __forceinline__ void ldsm_x4_t(uint32_t* r, uint32_t addr) {
    asm volatile("ldmatrix.sync.aligned.m8n8.x4.trans.shared.b16 {%0,%1,%2,%3}, [%4];"
                 : "=r"(r[0]), "=r"(r[1]), "=r"(r[2]), "=r"(r[3]) : "r"(addr));
}
__device__ __forceinline__ void mma16816(float* d, const uint32_t* a, const uint32_t* b) {
    asm volatile("mma.sync.aligned.m16n8k16.row.col.f32.f16.f16.f32 "
                 "{%0,%1,%2,%3}, {%4,%5,%6,%7}, {%8,%9}, {%0,%1,%2,%3};"
                 : "+f"(d[0]), "+f"(d[1]), "+f"(d[2]), "+f"(d[3])
                 : "r"(a[0]), "r"(a[1]), "r"(a[2]), "r"(a[3]), "r"(b[0]), "r"(b[1]));
}

// ════════════════ prep kernels ══════════════════════════════════════════
__global__ void repack_w_kernel(const float* __restrict__ rel_emb) {
    // 64 blocks: r = bx>>3, slice = bx&7 (2048 elems each)
    const int r = blockIdx.x >> 3;
    const int s0 = (blockIdx.x & 7) * 2048;
    for (int i = threadIdx.x; i < 2048; i += blockDim.x) {
        const int idx = s0 + i;
        const float w = rel_emb[r * DIM * DIM + idx];
        const __half h = __float2half(w);
        g_Wh[r][idx] = h;
        g_Wl[r][idx] = __float2half(w - __half2float(h));
    }
}

__global__ void hist_kernel(const int* __restrict__ dst, const int* __restrict__ rel, int n) {
    for (int i = blockIdx.x * blockDim.x + threadIdx.x; i < n; i += gridDim.x * blockDim.x)
        atomicAdd(&g_binCnt[(dst[i] >> 7) * NUM_RELS + rel[i]], 1);
}

__global__ void scan_kernel(int bins, int n_edges) {
    __shared__ int s_part[1024];
    const int tid = threadIdx.x;
    const int base = tid * 4;
    int v[4], sum = 0;
    #pragma unroll
    for (int q = 0; q < 4; q++) {
        const int b = base + q;
        v[q] = (b < bins) ? g_binCnt[b] : 0;
        sum += v[q];
    }
    s_part[tid] = sum;
    __syncthreads();
    for (int off = 1; off < 1024; off <<= 1) {
        int x = 0;
        if (tid >= off) x = s_part[tid - off];
        __syncthreads();
        s_part[tid] += x;
        __syncthreads();
    }
    int run = s_part[tid] - sum;                 // exclusive
    #pragma unroll
    for (int q = 0; q < 4; q++) {
        const int b = base + q;
        if (b < bins) { g_binOff[b] = run; g_binCur[b] = run; run += v[q]; }
    }
    if (tid == 0) g_binOff[bins] = n_edges;
}

__global__ void scatter_kernel(const int* __restrict__ dst, const int* __restrict__ rel, int n) {
    for (int i = blockIdx.x * blockDim.x + threadIdx.x; i < n; i += gridDim.x * blockDim.x) {
        const int key = (dst[i] >> 7) * NUM_RELS + rel[i];
        const int p = atomicAdd(&g_binCur[key], 1);
        g_eidx[p] = i;
    }
}

// ════════════════ fused aggregate + GEMM kernel ═════════════════════════
__global__ void __launch_bounds__(512, 1)
fused_kernel(const float* __restrict__ feat,
             const float* __restrict__ ew,
             const int*   __restrict__ src,
             const int*   __restrict__ dst,
             float*       __restrict__ out,
             int n_nodes)
{
    extern __shared__ char smem[];
    const uint32_t sbase = smem_u32(smem);
    const int tid  = threadIdx.x;
    const int wid  = tid >> 5;
    const int lane = tid & 31;
    const int t    = blockIdx.x;

    int*   s_src  = (int*)  (smem + OFF_SSRC);
    float* s_wv   = (float*)(smem + OFF_SW);
    int*   s_dl   = (int*)  (smem + OFF_SDL);
    int*   s_osrc = (int*)  (smem + OFF_OSRC);
    float* s_ow   = (float*)(smem + OFF_OW);
    int*   s_hist = (int*)  (smem + OFF_HIST);
    int*   s_rs   = (int*)  (smem + OFF_RS);
    int*   s_cur  = (int*)  (smem + OFF_CUR);

    const int n_rem = min(128, n_nodes - t * 128);

    // warp tiling for MMA: 4x4 warps, each 32x32
    const int m_base = (wid >> 2) * 32;
    const int n_base = (wid & 3) * 32;

    float accC[2][4][4];
    #pragma unroll
    for (int mt = 0; mt < 2; mt++)
        #pragma unroll
        for (int nt = 0; nt < 4; nt++)
            #pragma unroll
            for (int q = 0; q < 4; q++) accC[mt][nt][q] = 0.f;

    const uint32_t a_lane = (uint32_t)((lane & 15) * ROWB + (lane >> 4) * 16);
    const uint32_t b_lane = (uint32_t)((lane & 15) * ROWB + ((lane >> 4) & 1) * 16);

    for (int r = 0; r < NUM_RELS; r++) {
        const int key = t * NUM_RELS + r;
        const int bs  = g_binOff[key];
        const int be  = g_binOff[key + 1];

        // per-warp row accumulators (rows 8*wid .. 8*wid+7; lane -> 4 cols)
        float4 acc[8];
        #pragma unroll
        for (int q = 0; q < 8; q++) acc[q] = make_float4(0.f, 0.f, 0.f, 0.f);

        __syncthreads();   // also orders previous rel's MMA before staging reuse

        for (int c0 = bs; c0 < be; c0 += CAP) {
            const int c = min(CAP, be - c0);

            // stage edges
            for (int i = tid; i < c; i += 512) {
                const int e = g_eidx[c0 + i];
                s_src[i] = src[e];
                s_wv[i]  = ew[e];
                s_dl[i]  = dst[e] & 127;
            }
            if (tid < 128) s_hist[tid] = 0;
            __syncthreads();

            for (int i = tid; i < c; i += 512)
                atomicAdd(&s_hist[s_dl[i]], 1);
            __syncthreads();

            // warp 0: exclusive scan of 128 bins
            if (wid == 0) {
                const int b0 = lane * 4;
                const int v0 = s_hist[b0], v1 = s_hist[b0 + 1],
                          v2 = s_hist[b0 + 2], v3 = s_hist[b0 + 3];
                const int s = v0 + v1 + v2 + v3;
                int x = s;
                #pragma unroll
                for (int off = 1; off < 32; off <<= 1) {
                    const int y = __shfl_up_sync(0xFFFFFFFFu, x, off);
                    if (lane >= off) x += y;
                }
                const int excl = x - s;
                s_rs[b0]     = excl;            s_cur[b0]     = excl;
                s_rs[b0 + 1] = excl + v0;       s_cur[b0 + 1] = excl + v0;
                s_rs[b0 + 2] = excl + v0 + v1;  s_cur[b0 + 2] = excl + v0 + v1;
                s_rs[b0 + 3] = excl + v0 + v1 + v2;
                s_cur[b0 + 3] = s_rs[b0 + 3];
                if (lane == 31) s_rs[128] = excl + s;
            }
            __syncthreads();

            // scatter into dst-ordered arrays
            for (int i = tid; i < c; i += 512) {
                const int p = atomicAdd(&s_cur[s_dl[i]], 1);
                s_osrc[p] = s_src[i];
                s_ow[p]   = s_wv[i];
            }
            __syncthreads();

            // aggregation: warp w owns rows [8w, 8w+8)
            #pragma unroll
            for (int rr = 0; rr < 8; rr++) {
                int       j  = s_rs[8 * wid + rr];
                const int je = s_rs[8 * wid + rr + 1];
                for (; j + 1 < je; j += 2) {
                    const int   si0 = s_osrc[j],     si1 = s_osrc[j + 1];
                    const float w0  = s_ow[j],       w1  = s_ow[j + 1];
                    const float4 v0 = *(const float4*)(feat + (size_t)si0 * DIM + lane * 4);
                    const float4 v1 = *(const float4*)(feat + (size_t)si1 * DIM + lane * 4);
                    acc[rr].x += w0 * v0.x; acc[rr].y += w0 * v0.y;
                    acc[rr].z += w0 * v0.z; acc[rr].w += w0 * v0.w;
                    acc[rr].x += w1 * v1.x; acc[rr].y += w1 * v1.y;
                    acc[rr].z += w1 * v1.z; acc[rr].w += w1 * v1.w;
                }
                if (j < je) {
                    const int   si = s_osrc[j];
                    const float w  = s_ow[j];
                    const float4 v = *(const float4*)(feat + (size_t)si * DIM + lane * 4);
                    acc[rr].x += w * v.x; acc[rr].y += w * v.y;
                    acc[rr].z += w * v.z; acc[rr].w += w * v.w;
                }
            }
            __syncthreads();   // staging reused next chunk
        }

        // write A tile (fp16) — every row written, so no zeroing needed
        #pragma unroll
        for (int rr = 0; rr < 8; rr++) {
            const int row = 8 * wid + rr;
            __half2 h0, h1;
            h0.x = __float2half(acc[rr].x); h0.y = __float2half(acc[rr].y);
            h1.x = __float2half(acc[rr].z); h1.y = __float2half(acc[rr].w);
            uint2 pk;
            pk.x = *(uint32_t*)&h0; pk.y = *(uint32_t*)&h1;
            *(uint2*)(smem + OFF_A + row * ROWB + lane * 8) = pk;
        }

        // load W_r hi/lo into smem (padded rows)
        {
            const uint4* whg = (const uint4*)&g_Wh[r][0];
            const uint4* wlg = (const uint4*)&g_Wl[r][0];
            #pragma unroll
            for (int i = tid; i < 2048; i += 512) {
                const int row = i >> 4, c16 = i & 15;
                const int doff = row * ROWB + c16 * 16;
                *(uint4*)(smem + OFF_WHI + doff) = whg[i];
                *(uint4*)(smem + OFF_WLO + doff) = wlg[i];
            }
        }
        __syncthreads();

        // MMA: 8 k16-steps x 2 chains (Whi, Wlo)
        #pragma unroll
        for (int ks = 0; ks < 8; ks++) {
            uint32_t afr[2][4];
            #pragma unroll
            for (int mt = 0; mt < 2; mt++)
                ldsm_x4(afr[mt], sbase + OFF_A + (uint32_t)((m_base + mt * 16) * ROWB)
                                 + a_lane + (uint32_t)(ks * 32));
            #pragma unroll
            for (int ch = 0; ch < 2; ch++) {
                const uint32_t Wb = sbase + (ch ? OFF_WLO : OFF_WHI);
                uint32_t bfr[2][4];
                #pragma unroll
                for (int p = 0; p < 2; p++)
                    ldsm_x4_t(bfr[p], Wb + (uint32_t)(ks * 16 * ROWB) + b_lane
                                         + (uint32_t)((n_base + p * 16) * 2));
                #pragma unroll
                for (int mt = 0; mt < 2; mt++)
                    #pragma unroll
                    for (int p = 0; p < 2; p++) {
                        mma16816(accC[mt][2 * p + 0], afr[mt], &bfr[p][0]);
                        mma16816(accC[mt][2 * p + 1], afr[mt], &bfr[p][2]);
                    }
            }
        }
        // (barriers at the top of the next rel iteration order MMA vs smem reuse)
    }
    __syncthreads();   // MMA done; A/W regions reusable as C staging

    // stage C then coalesced guarded stores — no atomics
    {
        float* Cst = (float*)smem;
        const int grp = lane >> 2;
        const int tig = lane & 3;
        #pragma unroll
        for (int mt = 0; mt < 2; mt++) {
            const int r0 = m_base + mt * 16 + grp;
            #pragma unroll
            for (int nt = 0; nt < 4; nt++) {
                const int col = n_base + nt * 8 + tig * 2;
                *(float2*)&Cst[r0 * CSTRIDE + col]       = make_float2(accC[mt][nt][0], accC[mt][nt][1]);
                *(float2*)&Cst[(r0 + 8) * CSTRIDE + col] = make_float2(accC[mt][nt][2], accC[mt][nt][3]);
            }
        }
    }
    __syncthreads();
    {
        const float* Cst = (const float*)smem;
        const int row = tid >> 2;          // 0..127
        const int seg = tid & 3;           // 32-float segment
        if (row < n_rem) {
            float4* op = (float4*)(out + (size_t)(t * 128 + row) * DIM + seg * 32);
            const float* cp = &Cst[row * CSTRIDE + seg * 32];
            #pragma unroll
            for (int j = 0; j < 8; j++)
                op[j] = *(const float4*)(cp + j * 4);
        }
    }
}

// ════════════════ launch ════════════════════════════════════════════════
extern "C" void kernel_launch(void* const* d_in, const int* in_sizes, int n_in,
                              void* d_out, int out_size)
{
    const float* feat    = (const float*)d_in[0];
    const float* rel_emb = (const float*)d_in[1];
    const float* ew      = (const float*)d_in[2];
    const int*   src     = (const int*)d_in[3];
    const int*   dst     = (const int*)d_in[4];
    const int*   rel     = (const int*)d_in[5];
    float*       out     = (float*)d_out;

    const int n_edges = in_sizes[2];
    const int n_nodes = in_sizes[0] / DIM;
    const int tiles   = (n_nodes + 127) / 128;
    const int bins    = tiles * NUM_RELS;

    static void* binCnt_ptr = nullptr;
    static int attr_set = 0;
    if (!attr_set) {
        cudaGetSymbolAddress(&binCnt_ptr, g_binCnt);
        cudaFuncSetAttribute(fused_kernel,
                             cudaFuncAttributeMaxDynamicSharedMemorySize, SMEM_F);
        attr_set = 1;
    }

    cudaMemsetAsync(binCnt_ptr, 0, (size_t)bins * sizeof(int), 0);
    repack_w_kernel<<<64, 256>>>(rel_emb);
    hist_kernel<<<1024, 256>>>(dst, rel, n_edges);
    scan_kernel<<<1, 1024>>>(bins, n_edges);
    scatter_kernel<<<1024, 256>>>(dst, rel, n_edges);
    fused_kernel<<<tiles, 512, SMEM_F>>>(feat, ew, src, dst, out, n_nodes);
}